// round 1
// baseline (speedup 1.0000x reference)
#include <cuda_runtime.h>
#include <cuda_bf16.h>

// GAT layer, fully fused, fp32 CUDA-core version with packed f32x2 FMA.
//   h = X @ W                       (8192x512 @ 512x128)
//   s1 = h@a1, s2 = h@a2 ; E=exp(s), F=exp(0.2 s)   (separable leaky-relu-exp)
//   w_ij = adj ? (s1_i+s2_j>0 ? E1_i*E2_j : F1_i*F2_j) : 0   (no max-shift needed)
//   out_i = elu( (sum_j w_ij h_j) / (sum_j w_ij) )

typedef unsigned long long ull;

#define FMA2(acc, a, b) asm("fma.rn.f32x2 %0, %1, %2, %0;" : "+l"(acc) : "l"(a), "l"(b))
#define PACK2(d, s)     asm("mov.b64 %0, {%1, %1};" : "=l"(d) : "f"(s))
#define UNPACK2(lo, hi, s) asm("mov.b64 {%0, %1}, %2;" : "=f"(lo), "=f"(hi) : "l"(s))

constexpr int N    = 8192;
constexpr int FIN  = 512;
constexpr int FOUT = 128;
constexpr int TI   = 32;   // i-rows per CTA in aggregation kernel
constexpr int JB   = 32;   // j-chunk

__device__ float g_h[N * FOUT];
__device__ float g_s1[N], g_s2[N];
__device__ float g_E1[N], g_F1[N], g_E2[N], g_F2[N];

// ---------------------------------------------------------------------------
// Kernel A: h = X @ W   (BM=64, BN=128(full), BK=32), f32x2 packed FMA
// ---------------------------------------------------------------------------
__global__ void __launch_bounds__(256) k_gemm_hw(const float* __restrict__ X,
                                                 const float* __restrict__ W) {
    __shared__ float sX[64][32];    // 8KB
    __shared__ float sB[32][FOUT];  // 16KB
    const int t = threadIdx.x;
    const int tx = t & 31, ty = t >> 5;   // tx -> 4 cols, ty+8k -> 8 rows
    const int m0 = blockIdx.x * 64;

    const int xr = t >> 2, xc0 = (t & 3) * 8;
    const int wr = t >> 3, wc0 = (t & 7) * 16;

    ull acc[8][2] = {};

    for (int kc = 0; kc < FIN / 32; ++kc) {
        const int k0 = kc * 32;
        __syncthreads();
        {
            float4*       dx = reinterpret_cast<float4*>(&sX[xr][xc0]);
            const float4* sx = reinterpret_cast<const float4*>(X + (size_t)(m0 + xr) * FIN + k0 + xc0);
            dx[0] = sx[0]; dx[1] = sx[1];
            float4*       dw = reinterpret_cast<float4*>(&sB[wr][wc0]);
            const float4* sw = reinterpret_cast<const float4*>(W + (size_t)(k0 + wr) * FOUT + wc0);
            dw[0] = sw[0]; dw[1] = sw[1]; dw[2] = sw[2]; dw[3] = sw[3];
        }
        __syncthreads();
        #pragma unroll 8
        for (int kk = 0; kk < 32; ++kk) {
            ulonglong2 b2 = *reinterpret_cast<const ulonglong2*>(&sB[kk][tx << 2]);
            #pragma unroll
            for (int k = 0; k < 8; ++k) {
                ull ap;
                PACK2(ap, sX[ty + 8 * k][kk]);
                FMA2(acc[k][0], ap, b2.x);
                FMA2(acc[k][1], ap, b2.y);
            }
        }
    }
    #pragma unroll
    for (int k = 0; k < 8; ++k) {
        const int r = m0 + ty + 8 * k;
        float4 o;
        UNPACK2(o.x, o.y, acc[k][0]);
        UNPACK2(o.z, o.w, acc[k][1]);
        reinterpret_cast<float4*>(g_h + (size_t)r * FOUT)[tx] = o;
    }
}

// ---------------------------------------------------------------------------
// Kernel B: s1, s2 and the four exp vectors. One block (128 thr) per row.
// ---------------------------------------------------------------------------
__global__ void __launch_bounds__(128) k_scores(const float* __restrict__ a) {
    const int i = blockIdx.x;
    const int t = threadIdx.x;
    const float hv = g_h[(size_t)i * FOUT + t];
    float p1 = hv * __ldg(&a[t]);
    float p2 = hv * __ldg(&a[FOUT + t]);
    #pragma unroll
    for (int off = 16; off; off >>= 1) {
        p1 += __shfl_xor_sync(0xffffffffu, p1, off);
        p2 += __shfl_xor_sync(0xffffffffu, p2, off);
    }
    __shared__ float r1[4], r2[4];
    const int w = t >> 5;
    if ((t & 31) == 0) { r1[w] = p1; r2[w] = p2; }
    __syncthreads();
    if (t == 0) {
        const float s1 = r1[0] + r1[1] + r1[2] + r1[3];
        const float s2 = r2[0] + r2[1] + r2[2] + r2[3];
        g_s1[i] = s1;  g_s2[i] = s2;
        g_E1[i] = __expf(s1);        g_F1[i] = __expf(0.2f * s1);
        g_E2[i] = __expf(s2);        g_F2[i] = __expf(0.2f * s2);
    }
}

// ---------------------------------------------------------------------------
// Kernel C: fused masked softmax + weighted sum + elu.
// CTA: 32 i-rows x all 8192 j. 256 threads. Per thread: 4 rows x 4 cols accum.
// ---------------------------------------------------------------------------
__device__ __forceinline__ float elu_f(float v) { return v > 0.f ? v : expm1f(v); }

__global__ void __launch_bounds__(256, 2) k_gat_agg(const int* __restrict__ adj,
                                                    float* __restrict__ out) {
    __shared__ float sH[JB][FOUT];   // 16KB h tile
    __shared__ float sW[TI][JB];     // 4KB weight tile
    __shared__ float sS1[TI], sE1[TI], sF1[TI], sDen[TI];

    const int t = threadIdx.x;
    const int tx = t & 31, ty = t >> 5;       // tx -> f group (4 cols), jj lane; ty -> row group
    const int i0 = blockIdx.x * TI;

    if (t < TI) {
        sS1[t] = g_s1[i0 + t];
        sE1[t] = g_E1[i0 + t];
        sF1[t] = g_F1[i0 + t];
    }

    ull acc[4][2] = {};
    float dpart[4] = {0.f, 0.f, 0.f, 0.f};

    const int hr = t >> 3, hc = (t & 7) << 4;  // h-tile loader mapping

    for (int c = 0; c < N / JB; ++c) {
        const int j0 = c * JB;
        __syncthreads();
        // --- stage h tile (from L2-resident g_h) ---
        {
            const float4* hp = reinterpret_cast<const float4*>(g_h + (size_t)(j0 + hr) * FOUT + hc);
            float4*       sp = reinterpret_cast<float4*>(&sH[hr][hc]);
            sp[0] = hp[0]; sp[1] = hp[1]; sp[2] = hp[2]; sp[3] = hp[3];
        }
        // --- compute weights for 32x32 pairs; fold denominator partials ---
        {
            const float s2j = g_s2[j0 + tx];
            const float e2  = g_E2[j0 + tx];
            const float f2  = g_F2[j0 + tx];
            #pragma unroll
            for (int p = 0; p < 4; ++p) {
                const int il = ty + 8 * p;
                const int av = __ldg(&adj[(i0 + il) * N + j0 + tx]);
                const float x = sS1[il] + s2j;
                float w = (x > 0.f) ? sE1[il] * e2 : sF1[il] * f2;
                w = av ? w : 0.f;
                sW[il][tx] = w;
                dpart[p] += w;
            }
        }
        __syncthreads();
        // --- rank-1 accumulate: acc[r][f] += w[r][jj] * h[jj][f] ---
        #pragma unroll 8
        for (int jj = 0; jj < JB; ++jj) {
            ulonglong2 h2 = *reinterpret_cast<const ulonglong2*>(&sH[jj][tx << 2]);
            #pragma unroll
            for (int k = 0; k < 4; ++k) {
                ull wp;
                PACK2(wp, sW[ty + 8 * k][jj]);
                FMA2(acc[k][0], wp, h2.x);
                FMA2(acc[k][1], wp, h2.y);
            }
        }
    }

    // --- denominators: lanes of warp ty hold partials over jj for rows ty+8p ---
    #pragma unroll
    for (int p = 0; p < 4; ++p) {
        float v = dpart[p];
        #pragma unroll
        for (int off = 16; off; off >>= 1) v += __shfl_xor_sync(0xffffffffu, v, off);
        if (tx == 0) sDen[ty + 8 * p] = v;
    }
    __syncthreads();

    // --- normalize + elu + store ---
    #pragma unroll
    for (int k = 0; k < 4; ++k) {
        const int r = ty + 8 * k;
        const float inv = 1.f / sDen[r];
        float4 o;
        float lo, hi;
        UNPACK2(lo, hi, acc[k][0]);
        o.x = elu_f(lo * inv); o.y = elu_f(hi * inv);
        UNPACK2(lo, hi, acc[k][1]);
        o.z = elu_f(lo * inv); o.w = elu_f(hi * inv);
        reinterpret_cast<float4*>(out + (size_t)(i0 + r) * FOUT)[tx] = o;
    }
}

// ---------------------------------------------------------------------------
extern "C" void kernel_launch(void* const* d_in, const int* in_sizes, int n_in,
                              void* d_out, int out_size) {
    const float* X   = (const float*)d_in[0];   // 8192 x 512
    const int*   adj = (const int*)  d_in[1];   // 8192 x 8192
    const float* W   = (const float*)d_in[2];   // 512 x 128
    const float* a   = (const float*)d_in[3];   // 256 x 1
    float*       out = (float*)d_out;           // 8192 x 128

    k_gemm_hw<<<N / 64, 256>>>(X, W);
    k_scores<<<N, 128>>>(a);
    k_gat_agg<<<N / TI, 256>>>(adj, out);
}